// round 9
// baseline (speedup 1.0000x reference)
#include <cuda_runtime.h>

// TransOp_expm via traceless Cayley-Hamilton, 2 batches/thread packed f32x2.
// R9: cp.async.bulk staging — CTA-wide bulk copies gmem<->smem replace all
// per-thread LDG/STG (L1tex wavefronts were the binding floor).
// NSQ=3, ORDER=10.

#define NSQ 3
#define NORD 10

typedef unsigned long long ull;

__device__ __forceinline__ ull pk(float lo, float hi) {
    ull r; asm("mov.b64 %0, {%1, %2};" : "=l"(r) : "f"(lo), "f"(hi)); return r;
}
__device__ __forceinline__ void upk(ull v, float& lo, float& hi) {
    asm("mov.b64 {%0, %1}, %2;" : "=f"(lo), "=f"(hi) : "l"(v));
}
__device__ __forceinline__ ull fma2(ull a, ull b, ull c) {
    ull d; asm("fma.rn.f32x2 %0, %1, %2, %3;" : "=l"(d) : "l"(a), "l"(b), "l"(c)); return d;
}
__device__ __forceinline__ ull mul2(ull a, ull b) {
    ull d; asm("mul.rn.f32x2 %0, %1, %2;" : "=l"(d) : "l"(a), "l"(b)); return d;
}
__device__ __forceinline__ ull add2(ull a, ull b) {
    ull d; asm("add.rn.f32x2 %0, %1, %2;" : "=l"(d) : "l"(a), "l"(b)); return d;
}
__device__ __forceinline__ ull bcast(float v) { return pk(v, v); }

__device__ __forceinline__ unsigned smem_u32(const void* p) {
    unsigned a;
    asm("{ .reg .u64 t; cvta.to.shared.u64 t, %1; cvt.u32.u64 %0, t; }"
        : "=r"(a) : "l"(p));
    return a;
}
__device__ __forceinline__ ull gptr(const void* p) {
    ull g; asm("cvta.to.global.u64 %0, %1;" : "=l"(g) : "l"(p)); return g;
}

// Traceless-CH core (same math as R8): cm packed coeffs, v packed x -> y packed.
__device__ __forceinline__ void expm_core(
    const ull* __restrict__ s_psi,
    const ull cm[6], ull v0, ull v1, ull v2,
    ull& y0, ull& y1, ull& y2)
{
    ull nc2, c3, emu;
    ull w0, w1, w2, u0, u1, u2;
    {
        const ull NEG1 = bcast(-1.0f);
        ull A[9];
        {
            const ulonglong2* sv = (const ulonglong2*)s_psi;
            ulonglong2 p0 = sv[0], p1 = sv[1], p2 = sv[2], p3 = sv[3];
            ull p8 = s_psi[8];
            A[0] = mul2(cm[0], p0.x); A[1] = mul2(cm[0], p0.y);
            A[2] = mul2(cm[0], p1.x); A[3] = mul2(cm[0], p1.y);
            A[4] = mul2(cm[0], p2.x); A[5] = mul2(cm[0], p2.y);
            A[6] = mul2(cm[0], p3.x); A[7] = mul2(cm[0], p3.y);
            A[8] = mul2(cm[0], p8);
            #pragma unroll
            for (int m = 1; m < 6; m++) {
                ulonglong2 r0 = sv[m * 5 + 0], r1 = sv[m * 5 + 1];
                ulonglong2 r2 = sv[m * 5 + 2], r3 = sv[m * 5 + 3];
                ull r8 = s_psi[m * 10 + 8];
                A[0] = fma2(cm[m], r0.x, A[0]); A[1] = fma2(cm[m], r0.y, A[1]);
                A[2] = fma2(cm[m], r1.x, A[2]); A[3] = fma2(cm[m], r1.y, A[3]);
                A[4] = fma2(cm[m], r2.x, A[4]); A[5] = fma2(cm[m], r2.y, A[5]);
                A[6] = fma2(cm[m], r3.x, A[6]); A[7] = fma2(cm[m], r3.y, A[7]);
                A[8] = fma2(cm[m], r8, A[8]);
            }
        }

        ull c1 = add2(add2(A[0], A[4]), A[8]);
        {
            float c1lo, c1hi;
            upk(c1, c1lo, c1hi);
            const float s = (float)(1 << NSQ) / 3.0f;
            emu = pk(__expf(c1lo * s), __expf(c1hi * s));
        }
        ull nmu = mul2(c1, bcast(-1.0f / 3.0f));
        A[0] = add2(A[0], nmu);
        A[4] = add2(A[4], nmu);
        A[8] = add2(A[8], nmu);

        ull tt = fma2(A[2], A[6], mul2(A[1], A[3]));
        tt = fma2(A[5], A[7], tt);
        ull ss = fma2(A[4], A[4], mul2(A[0], A[0]));
        ss = fma2(A[8], A[8], ss);
        nc2 = fma2(ss, bcast(0.5f), tt);

        ull m0  = fma2(mul2(A[5], A[7]), NEG1, mul2(A[4], A[8]));
        ull m1n = fma2(mul2(A[3], A[8]), NEG1, mul2(A[5], A[6]));
        ull m2  = fma2(mul2(A[4], A[6]), NEG1, mul2(A[3], A[7]));
        c3  = fma2(A[0], m0, fma2(A[1], m1n, mul2(A[2], m2)));

        w0 = fma2(A[0], v0, fma2(A[1], v1, mul2(A[2], v2)));
        w1 = fma2(A[3], v0, fma2(A[4], v1, mul2(A[5], v2)));
        w2 = fma2(A[6], v0, fma2(A[7], v1, mul2(A[8], v2)));
        u0 = fma2(A[0], w0, fma2(A[1], w1, mul2(A[2], w2)));
        u1 = fma2(A[3], w0, fma2(A[4], w1, mul2(A[5], w2)));
        u2 = fma2(A[6], w0, fma2(A[7], w1, mul2(A[8], w2)));
    }

    const float invfact[NORD + 1] = {
        1.f, 1.f, 0.5f, 1.f/6.f, 1.f/24.f, 1.f/120.f, 1.f/720.f,
        1.f/5040.f, 1.f/40320.f, 1.f/362880.f, 1.f/3628800.f
    };
    ull sa = bcast(invfact[NORD]), sb = 0ULL, sc = 0ULL;
    #pragma unroll
    for (int k = NORD - 1; k >= 0; k--) {
        ull oc = sc;
        ull na = fma2(c3,  oc, bcast(invfact[k]));
        ull nb = fma2(nc2, oc, sa);
        sc = sb;
        sa = na;
        sb = nb;
    }

    #pragma unroll
    for (int sq = 0; sq < NSQ; sq++) {
        ull bc  = mul2(sb, sc);
        ull bc2 = add2(bc, bc);
        ull cc  = mul2(sc, sc);
        ull ab  = mul2(sa, sb);
        ull ab2 = add2(ab, ab);
        ull ac  = mul2(sa, sc);
        ull ac2 = add2(ac, ac);
        ull na  = fma2(bc2, c3, mul2(sa, sa));
        ull nb  = fma2(cc, c3, fma2(bc2, nc2, ab2));
        ull ncc = fma2(cc, nc2, fma2(sb, sb, ac2));
        sa = na; sb = nb; sc = ncc;
    }

    sa = mul2(sa, emu);
    sb = mul2(sb, emu);
    sc = mul2(sc, emu);
    y0 = fma2(sa, v0, fma2(sb, w0, mul2(sc, u0)));
    y1 = fma2(sa, v1, fma2(sb, w1, mul2(sc, u1)));
    y2 = fma2(sa, v2, fma2(sb, w2, mul2(sc, u2)));
}

#define TILE_B 512                   // batches per CTA (256 threads x 2)
#define C_BYTES (TILE_B * 6 * 4)     // 12288
#define X_BYTES (TILE_B * 3 * 4)     // 6144
#define O_BYTES (TILE_B * 3 * 4)     // 6144

__global__ __launch_bounds__(256) void expmch9_kernel(
    const float* __restrict__ x,
    const float* __restrict__ c,
    const float* __restrict__ psi,
    float* __restrict__ out,
    int B)
{
    __shared__ __align__(16) ull   s_psi[60];
    __shared__ __align__(8)  ull   s_mbar;
    __shared__ __align__(16) float s_c[TILE_B * 6];
    __shared__ __align__(16) float s_x[TILE_B * 3];
    __shared__ __align__(16) float s_o[TILE_B * 3];

    int tid = threadIdx.x;
    long long base = (long long)blockIdx.x * TILE_B;
    bool cta_full = (base + TILE_B <= (long long)B);

    if (tid < 60) {
        int row = tid / 10, col = tid % 10;
        float v = (col < 9) ? psi[row * 9 + col] * (1.0f / (float)(1 << NSQ)) : 0.0f;
        s_psi[tid] = pk(v, v);
    }
    unsigned mb = smem_u32(&s_mbar);
    if (cta_full && tid == 0) {
        asm volatile("mbarrier.init.shared.b64 [%0], 1;" :: "r"(mb) : "memory");
    }
    __syncthreads();

    if (cta_full) {
        if (tid == 0) {
            asm volatile("mbarrier.arrive.expect_tx.shared.b64 _, [%0], %1;"
                         :: "r"(mb), "r"((unsigned)(C_BYTES + X_BYTES)) : "memory");
            unsigned sc_a = smem_u32(s_c);
            unsigned sx_a = smem_u32(s_x);
            ull gc = gptr(c + base * 6);
            ull gx = gptr(x + base * 3);
            asm volatile(
                "cp.async.bulk.shared::cluster.global.mbarrier::complete_tx::bytes "
                "[%0], [%1], %2, [%3];"
                :: "r"(sc_a), "l"(gc), "r"((unsigned)C_BYTES), "r"(mb) : "memory");
            asm volatile(
                "cp.async.bulk.shared::cluster.global.mbarrier::complete_tx::bytes "
                "[%0], [%1], %2, [%3];"
                :: "r"(sx_a), "l"(gx), "r"((unsigned)X_BYTES), "r"(mb) : "memory");
        }
        // all threads wait for the tile (acquire: generic LDS follows)
        asm volatile(
            "{\n\t"
            ".reg .pred P;\n"
            "W%=:\n\t"
            "mbarrier.try_wait.parity.acquire.cta.shared::cta.b64 P, [%0], 0, 0x989680;\n\t"
            "@P bra D%=;\n\t"
            "bra.uni W%=;\n"
            "D%=:\n\t"
            "}"
            :: "r"(mb) : "memory");

        // ---- per-thread data from smem ----
        const float4* cq = (const float4*)(s_c + tid * 12);
        float4 q0 = cq[0], q1 = cq[1], q2 = cq[2];
        const float2* xq = (const float2*)(s_x + tid * 6);
        float2 f0 = xq[0], f1 = xq[1], f2 = xq[2];

        ull cm[6];
        cm[0] = pk(q0.x, q1.z);
        cm[1] = pk(q0.y, q1.w);
        cm[2] = pk(q0.z, q2.x);
        cm[3] = pk(q0.w, q2.y);
        cm[4] = pk(q1.x, q2.z);
        cm[5] = pk(q1.y, q2.w);
        ull v0 = pk(f0.x, f1.y);
        ull v1 = pk(f0.y, f2.x);
        ull v2 = pk(f1.x, f2.y);

        ull y0, y1, y2;
        expm_core(s_psi, cm, v0, v1, v2, y0, y1, y2);

        float y0a, y0b, y1a, y1b, y2a, y2b;
        upk(y0, y0a, y0b); upk(y1, y1a, y1b); upk(y2, y2a, y2b);
        float2* oq = (float2*)(s_o + tid * 6);
        oq[0] = make_float2(y0a, y1a);
        oq[1] = make_float2(y2a, y0b);
        oq[2] = make_float2(y1b, y2b);

        __syncthreads();
        if (tid == 0) {
            asm volatile("fence.proxy.async.shared::cta;" ::: "memory");
            unsigned so_a = smem_u32(s_o);
            ull go = gptr(out + base * 3);
            asm volatile(
                "cp.async.bulk.global.shared::cta.bulk_group [%0], [%1], %2;"
                :: "l"(go), "r"(so_a), "r"((unsigned)O_BYTES) : "memory");
            asm volatile("cp.async.bulk.commit_group;" ::: "memory");
            asm volatile("cp.async.bulk.wait_group 0;" ::: "memory");
        }
    } else {
        // ---- fallback tail CTA: direct gmem path ----
        int b0 = (int)base + 2 * tid;
        if (b0 >= B) return;
        bool full = (b0 + 1 < B);
        ull cm[6], v0, v1, v2;
        if (full) {
            const float4* cq = (const float4*)(c + b0 * 6);
            float4 q0 = __ldg(&cq[0]);
            float4 q1 = __ldg(&cq[1]);
            float4 q2 = __ldg(&cq[2]);
            const float2* xq = (const float2*)(x + b0 * 3);
            float2 f0 = __ldg(&xq[0]);
            float2 f1 = __ldg(&xq[1]);
            float2 f2 = __ldg(&xq[2]);
            cm[0] = pk(q0.x, q1.z);
            cm[1] = pk(q0.y, q1.w);
            cm[2] = pk(q0.z, q2.x);
            cm[3] = pk(q0.w, q2.y);
            cm[4] = pk(q1.x, q2.z);
            cm[5] = pk(q1.y, q2.w);
            v0 = pk(f0.x, f1.y);
            v1 = pk(f0.y, f2.x);
            v2 = pk(f1.x, f2.y);
        } else {
            const float* cb = c + b0 * 6;
            #pragma unroll
            for (int m = 0; m < 6; m++) { float v = __ldg(&cb[m]); cm[m] = pk(v, v); }
            const float* xb = x + b0 * 3;
            float x0 = __ldg(&xb[0]), x1 = __ldg(&xb[1]), x2 = __ldg(&xb[2]);
            v0 = pk(x0, x0); v1 = pk(x1, x1); v2 = pk(x2, x2);
        }
        ull y0, y1, y2;
        expm_core(s_psi, cm, v0, v1, v2, y0, y1, y2);
        if (full) {
            float y0a, y0b, y1a, y1b, y2a, y2b;
            upk(y0, y0a, y0b); upk(y1, y1a, y1b); upk(y2, y2a, y2b);
            float2* oq = (float2*)(out + b0 * 3);
            oq[0] = make_float2(y0a, y1a);
            oq[1] = make_float2(y2a, y0b);
            oq[2] = make_float2(y1b, y2b);
        } else {
            float lo, hi;
            float* ob = out + b0 * 3;
            upk(y0, lo, hi); ob[0] = lo;
            upk(y1, lo, hi); ob[1] = lo;
            upk(y2, lo, hi); ob[2] = lo;
        }
    }
}

extern "C" void kernel_launch(void* const* d_in, const int* in_sizes, int n_in,
                              void* d_out, int out_size) {
    const float* x   = (const float*)d_in[0];  // [B,3,1]
    const float* c   = (const float*)d_in[1];  // [B,6]
    const float* psi = (const float*)d_in[2];  // [6,3,3]
    float* out = (float*)d_out;                // [B,3]

    int B = in_sizes[0] / 3;
    int blocks = (B + TILE_B - 1) / TILE_B;
    expmch9_kernel<<<blocks, 256>>>(x, c, psi, out, B);
}

// round 10
// speedup vs baseline: 1.1014x; 1.1014x over previous
#include <cuda_runtime.h>

// TransOp_expm via traceless Cayley-Hamilton, SCALAR fp32, 2 independent
// batches per thread (ILP from interleaving, not f32x2 packing — packed
// variant's pk/upk overhead + serial chain pinned issue at 44%).
// NSQ=3, ORDER=10.

#define NSQ 3
#define NORD 10

// Scalar traceless-CH core for one batch. A[9] consumed (by value semantics
// via registers), v in, y out.
__device__ __forceinline__ void expm_core_s(
    float A0, float A1, float A2, float A3, float A4,
    float A5, float A6, float A7, float A8,
    float v0, float v1, float v2,
    float& y0, float& y1, float& y2)
{
    // trace + exp prefactor (MUFU, issued early)
    float c1 = A0 + A4 + A8;
    float emu = __expf(c1 * ((float)(1 << NSQ) / 3.0f));
    // shift to traceless
    float mu = c1 * (1.0f / 3.0f);
    A0 -= mu; A4 -= mu; A8 -= mu;

    // nc2 = tr(Ab^2)/2 ; c3 = det(Ab)
    float tt = fmaf(A2, A6, A1 * A3);
    tt = fmaf(A5, A7, tt);
    float ss = fmaf(A4, A4, A0 * A0);
    ss = fmaf(A8, A8, ss);
    float nc2 = fmaf(ss, 0.5f, tt);

    float m0  = fmaf(A4, A8, -(A5 * A7));
    float m1n = fmaf(A5, A6, -(A3 * A8));
    float m2  = fmaf(A3, A7, -(A4 * A6));
    float c3  = fmaf(A0, m0, fmaf(A1, m1n, A2 * m2));

    // w = Ab v, u = Ab w
    float w0 = fmaf(A0, v0, fmaf(A1, v1, A2 * v2));
    float w1 = fmaf(A3, v0, fmaf(A4, v1, A5 * v2));
    float w2 = fmaf(A6, v0, fmaf(A7, v1, A8 * v2));
    float u0 = fmaf(A0, w0, fmaf(A1, w1, A2 * w2));
    float u1 = fmaf(A3, w0, fmaf(A4, w1, A5 * w2));
    float u2 = fmaf(A6, w0, fmaf(A7, w1, A8 * w2));

    // Horner Taylor (traceless): E = sa I + sb Ab + sc Ab^2
    const float invfact[NORD + 1] = {
        1.f, 1.f, 0.5f, 1.f/6.f, 1.f/24.f, 1.f/120.f, 1.f/720.f,
        1.f/5040.f, 1.f/40320.f, 1.f/362880.f, 1.f/3628800.f
    };
    float sa = invfact[NORD], sb = 0.0f, sc = 0.0f;
    #pragma unroll
    for (int k = NORD - 1; k >= 0; k--) {
        float oc = sc;
        float na = fmaf(c3,  oc, invfact[k]);
        float nb = fmaf(nc2, oc, sa);
        sc = sb;
        sa = na;
        sb = nb;
    }

    // squarings (Ab^3 = nc2 Ab + c3 I)
    #pragma unroll
    for (int sq = 0; sq < NSQ; sq++) {
        float bc2 = 2.0f * (sb * sc);
        float cc  = sc * sc;
        float ab2 = 2.0f * (sa * sb);
        float ac2 = 2.0f * (sa * sc);
        float na  = fmaf(bc2, c3, sa * sa);
        float nb  = fmaf(cc, c3, fmaf(bc2, nc2, ab2));
        float ncc = fmaf(cc, nc2, fmaf(sb, sb, ac2));
        sa = na; sb = nb; sc = ncc;
    }

    sa *= emu; sb *= emu; sc *= emu;
    y0 = fmaf(sa, v0, fmaf(sb, w0, sc * u0));
    y1 = fmaf(sa, v1, fmaf(sb, w1, sc * u1));
    y2 = fmaf(sa, v2, fmaf(sb, w2, sc * u2));
}

__global__ __launch_bounds__(256) void expmsc_kernel(
    const float* __restrict__ x,
    const float* __restrict__ c,
    const float* __restrict__ psi,
    float* __restrict__ out,
    int B)
{
    // psi pre-scaled by 1/2^NSQ; rows padded to 12 floats (16B-aligned)
    __shared__ __align__(16) float s_psi[72];
    if (threadIdx.x < 72) {
        int row = threadIdx.x / 12, col = threadIdx.x % 12;
        s_psi[threadIdx.x] =
            (col < 9) ? psi[row * 9 + col] * (1.0f / (float)(1 << NSQ)) : 0.0f;
    }
    __syncthreads();

    int t  = blockIdx.x * blockDim.x + threadIdx.x;
    int b0 = 2 * t;
    if (b0 >= B) return;
    bool full = (b0 + 1 < B);

    // ---- loads (vectorized pair layout, same as packed versions) ----
    float ca[6], cb[6];
    float va0, va1, va2, vb0, vb1, vb2;
    if (full) {
        const float4* cq = (const float4*)(c + b0 * 6);
        float4 q0 = __ldg(&cq[0]);
        float4 q1 = __ldg(&cq[1]);
        float4 q2 = __ldg(&cq[2]);
        ca[0] = q0.x; ca[1] = q0.y; ca[2] = q0.z; ca[3] = q0.w; ca[4] = q1.x; ca[5] = q1.y;
        cb[0] = q1.z; cb[1] = q1.w; cb[2] = q2.x; cb[3] = q2.y; cb[4] = q2.z; cb[5] = q2.w;
        const float2* xq = (const float2*)(x + b0 * 3);
        float2 f0 = __ldg(&xq[0]);
        float2 f1 = __ldg(&xq[1]);
        float2 f2 = __ldg(&xq[2]);
        va0 = f0.x; va1 = f0.y; va2 = f1.x;
        vb0 = f1.y; vb1 = f2.x; vb2 = f2.y;
    } else {
        const float* cp = c + b0 * 6;
        #pragma unroll
        for (int m = 0; m < 6; m++) { ca[m] = __ldg(&cp[m]); cb[m] = ca[m]; }
        const float* xb = x + b0 * 3;
        va0 = __ldg(&xb[0]); va1 = __ldg(&xb[1]); va2 = __ldg(&xb[2]);
        vb0 = va0; vb1 = va1; vb2 = va2;
    }

    // ---- build both A matrices sharing psi-row loads ----
    float Aa[9], Ab[9];
    {
        const float4* pr = (const float4*)s_psi;
        #pragma unroll
        for (int m = 0; m < 6; m++) {
            float4 p0 = pr[m * 3 + 0];
            float4 p1 = pr[m * 3 + 1];
            float  p8 = s_psi[m * 12 + 8];
            float cam = ca[m], cbm = cb[m];
            if (m == 0) {
                Aa[0] = cam * p0.x; Ab[0] = cbm * p0.x;
                Aa[1] = cam * p0.y; Ab[1] = cbm * p0.y;
                Aa[2] = cam * p0.z; Ab[2] = cbm * p0.z;
                Aa[3] = cam * p0.w; Ab[3] = cbm * p0.w;
                Aa[4] = cam * p1.x; Ab[4] = cbm * p1.x;
                Aa[5] = cam * p1.y; Ab[5] = cbm * p1.y;
                Aa[6] = cam * p1.z; Ab[6] = cbm * p1.z;
                Aa[7] = cam * p1.w; Ab[7] = cbm * p1.w;
                Aa[8] = cam * p8;   Ab[8] = cbm * p8;
            } else {
                Aa[0] = fmaf(cam, p0.x, Aa[0]); Ab[0] = fmaf(cbm, p0.x, Ab[0]);
                Aa[1] = fmaf(cam, p0.y, Aa[1]); Ab[1] = fmaf(cbm, p0.y, Ab[1]);
                Aa[2] = fmaf(cam, p0.z, Aa[2]); Ab[2] = fmaf(cbm, p0.z, Ab[2]);
                Aa[3] = fmaf(cam, p0.w, Aa[3]); Ab[3] = fmaf(cbm, p0.w, Ab[3]);
                Aa[4] = fmaf(cam, p1.x, Aa[4]); Ab[4] = fmaf(cbm, p1.x, Ab[4]);
                Aa[5] = fmaf(cam, p1.y, Aa[5]); Ab[5] = fmaf(cbm, p1.y, Ab[5]);
                Aa[6] = fmaf(cam, p1.z, Aa[6]); Ab[6] = fmaf(cbm, p1.z, Ab[6]);
                Aa[7] = fmaf(cam, p1.w, Aa[7]); Ab[7] = fmaf(cbm, p1.w, Ab[7]);
                Aa[8] = fmaf(cam, p8,   Aa[8]); Ab[8] = fmaf(cbm, p8,   Ab[8]);
            }
        }
    }

    // ---- two independent scalar pipelines (ptxas interleaves) ----
    float ya0, ya1, ya2, yb0, yb1, yb2;
    expm_core_s(Aa[0], Aa[1], Aa[2], Aa[3], Aa[4], Aa[5], Aa[6], Aa[7], Aa[8],
                va0, va1, va2, ya0, ya1, ya2);
    expm_core_s(Ab[0], Ab[1], Ab[2], Ab[3], Ab[4], Ab[5], Ab[6], Ab[7], Ab[8],
                vb0, vb1, vb2, yb0, yb1, yb2);

    // ---- store ----
    if (full) {
        float2* oq = (float2*)(out + b0 * 3);
        oq[0] = make_float2(ya0, ya1);
        oq[1] = make_float2(ya2, yb0);
        oq[2] = make_float2(yb1, yb2);
    } else {
        float* ob = out + b0 * 3;
        ob[0] = ya0; ob[1] = ya1; ob[2] = ya2;
    }
}

extern "C" void kernel_launch(void* const* d_in, const int* in_sizes, int n_in,
                              void* d_out, int out_size) {
    const float* x   = (const float*)d_in[0];  // [B,3,1]
    const float* c   = (const float*)d_in[1];  // [B,6]
    const float* psi = (const float*)d_in[2];  // [6,3,3]
    float* out = (float*)d_out;                // [B,3]

    int B = in_sizes[0] / 3;
    int pairs = (B + 1) / 2;
    int threads = 256;
    int blocks = (pairs + threads - 1) / threads;
    expmsc_kernel<<<blocks, threads>>>(x, c, psi, out, B);
}